// round 14
// baseline (speedup 1.0000x reference)
#include <cuda_runtime.h>
#include <cuda_fp16.h>
#include <cstdint>

// Problem constants
#define TOKENS 2048
#define HIDDEN 2048
#define INTER  5632
#define NEXP   8
#define TOPK   2
#define NPAIR  4096

#define BM     128
#define BN1    64          // gemm1 n-tile
#define BN2    64          // gemm2 n-tile
#define MAXMT  32          // m-slots per expert

// ---- tcgen05 config: fp16 K-major SW128, BK=64, NSTG=2, 3 CTAs/SM ----
#define BK_TC 64
#define NSTG  2
#define A_TILE_B  (128 * 128)            // 128 rows x 64k fp16 = 16 KB
#define W_TILE_B  (64 * 128)             // 64 n x 64 k fp16 = 8 KB
#define G1_STAGE  (A_TILE_B + 2 * W_TILE_B)   // 32 KB
#define G2_STAGE  (A_TILE_B + W_TILE_B)       // 24 KB
#define SMEM_TMEM 0
#define SMEM_CONS 16
#define SMEM_DATA 1024
#define G1_SMEM (SMEM_DATA + NSTG * G1_STAGE)  // 66,560  -> 3 CTAs/SM
#define G2_SMEM (SMEM_DATA + NSTG * G2_STAGE)  // 50,176  -> 3 CTAs/SM

#define IDESC_G1 ((1u << 4) | ((BN1 / 8) << 17) | (8u << 24))   // M=128,N=64
#define IDESC_G2 ((1u << 4) | ((BN2 / 8) << 17) | (8u << 24))   // M=128,N=64

#define FSTR 36   // fallback smem stride

#if defined(__CUDA_ARCH__) && defined(__CUDA_ARCH_FEAT_SM103_ALL)
#define HAS_TCGEN05 1
#else
#define HAS_TCGEN05 0
#endif

// -------- persistent device scratch --------
__device__ int      d_cnt[NEXP];
__device__ int      d_off[NEXP];
__device__ int      d_tok[NPAIR];
__device__ int      d_pos[NPAIR];
__device__ uint32_t d_xg[(size_t)(NPAIR + 256) * (HIDDEN / 2)];   // sorted x fp16
__device__ uint32_t d_hbuf[(size_t)(NPAIR + 256) * (INTER / 2)];  // h fp16, padded
__device__ float    d_ybuf[(size_t)NPAIR * HIDDEN];

// ---------------------------------------------------------------------------
// helpers
// ---------------------------------------------------------------------------
__device__ __forceinline__ uint32_t packh2(float lo, float hi) {
    __half2 h = __floats2half2_rn(lo, hi);
    return *reinterpret_cast<uint32_t*>(&h);
}
__device__ __forceinline__ void mma16816(float c[4], const uint32_t a[4],
                                         uint32_t b0, uint32_t b1) {
    asm volatile(
        "mma.sync.aligned.m16n8k16.row.col.f32.f16.f16.f32 "
        "{%0,%1,%2,%3}, {%4,%5,%6,%7}, {%8,%9}, {%0,%1,%2,%3};\n"
        : "+f"(c[0]), "+f"(c[1]), "+f"(c[2]), "+f"(c[3])
        : "r"(a[0]), "r"(a[1]), "r"(a[2]), "r"(a[3]), "r"(b0), "r"(b1));
}
#define STS128(a, q0, q1, q2, q3)                                                 \
    asm volatile("st.shared.v4.b32 [%0], {%1,%2,%3,%4};"                          \
        :: "r"(a), "r"(q0), "r"(q1), "r"(q2), "r"(q3) : "memory")

#if HAS_TCGEN05
__device__ __forceinline__ uint32_t smem_u32(const void* p) {
    uint32_t a;
    asm("{ .reg .u64 t; cvta.to.shared.u64 t, %1; cvt.u32.u64 %0, t; }" : "=r"(a) : "l"(p));
    return a;
}
__device__ __forceinline__ uint32_t swz128(uint32_t b) { return b ^ ((b >> 3) & 0x70); }
static __device__ __forceinline__ uint64_t make_desc(uint32_t addr) {
    // K-major SW128: layout=2, version=1, SBO=64, LBO=1
    return ((uint64_t)2 << 61) | ((uint64_t)1 << 46) | ((uint64_t)64 << 32) |
           ((uint64_t)1 << 16) | ((uint64_t)(addr >> 4) & 0x3FFF);
}

#define MBAR_INIT(a, c) \
    asm volatile("mbarrier.init.shared.b64 [%0], %1;" :: "r"(a), "r"(c) : "memory")
#define MBAR_WAIT(a, ph) do {                                                     \
    uint32_t _m = (a), _p = (ph), _d;                                             \
    asm volatile("{\n\t.reg .pred p;\n\t"                                         \
        "mbarrier.try_wait.parity.acquire.cta.shared::cta.b64 p, [%1], %2;\n\t"   \
        "selp.b32 %0, 1, 0, p;\n\t}" : "=r"(_d) : "r"(_m), "r"(_p) : "memory");   \
    if (!_d) {                                                                     \
        asm volatile("{\n\t.reg .pred P1;\n\t"                                    \
        "W%=:\n\t"                                                                \
        "mbarrier.try_wait.parity.acquire.cta.shared::cta.b64 P1, [%0], %1, 0x989680;\n\t" \
        "@P1 bra.uni D%=;\n\t bra.uni W%=;\n\t D%=:\n\t}"                        \
        :: "r"(_m), "r"(_p) : "memory");                                          \
    } } while (0)

#define TC_ALLOC(sa, n)  asm volatile("tcgen05.alloc.cta_group::1.sync.aligned.shared::cta.b32 [%0], %1;" :: "r"(sa), "r"(n) : "memory")
#define TC_DEALLOC(t, n) asm volatile("tcgen05.dealloc.cta_group::1.sync.aligned.b32 %0, %1;" :: "r"(t), "r"(n))
#define TC_RELINQ()      asm volatile("tcgen05.relinquish_alloc_permit.cta_group::1.sync.aligned;")
#define TC_COMMIT(a)     asm volatile("tcgen05.commit.cta_group::1.mbarrier::arrive::one.shared::cluster.b64 [%0];" :: "r"(a) : "memory")
#define TC_FENCE_AFTER() asm volatile("tcgen05.fence::after_thread_sync;" ::: "memory")
#define TC_WAIT_LD()     asm volatile("tcgen05.wait::ld.sync.aligned;" ::: "memory")
#define FENCE_ASYNC()    asm volatile("fence.proxy.async.shared::cta;" ::: "memory")

__device__ __forceinline__ void mma_f16_ss(uint32_t d, uint64_t ad, uint64_t bd,
                                           uint32_t idesc, uint32_t en) {
    asm volatile(
        "{\n\t.reg .pred p;\n\t"
        "setp.ne.u32 p, %4, 0;\n\t"
        "tcgen05.mma.cta_group::1.kind::f16 [%0], %1, %2, %3, {%5, %5, %5, %5}, p;\n\t"
        "}" :: "r"(d), "l"(ad), "l"(bd), "r"(idesc), "r"(en), "r"(0u) : "memory");
}

#define LDTM_X32(r, a)                                                            \
    asm volatile("tcgen05.ld.sync.aligned.32x32b.x32.b32 "                        \
        "{%0,%1,%2,%3,%4,%5,%6,%7,%8,%9,%10,%11,%12,%13,%14,%15,"                 \
        "%16,%17,%18,%19,%20,%21,%22,%23,%24,%25,%26,%27,%28,%29,%30,%31}, [%32];"\
        : "=r"((r)[0]),"=r"((r)[1]),"=r"((r)[2]),"=r"((r)[3]),                    \
          "=r"((r)[4]),"=r"((r)[5]),"=r"((r)[6]),"=r"((r)[7]),                    \
          "=r"((r)[8]),"=r"((r)[9]),"=r"((r)[10]),"=r"((r)[11]),                  \
          "=r"((r)[12]),"=r"((r)[13]),"=r"((r)[14]),"=r"((r)[15]),                \
          "=r"((r)[16]),"=r"((r)[17]),"=r"((r)[18]),"=r"((r)[19]),                \
          "=r"((r)[20]),"=r"((r)[21]),"=r"((r)[22]),"=r"((r)[23]),                \
          "=r"((r)[24]),"=r"((r)[25]),"=r"((r)[26]),"=r"((r)[27]),                \
          "=r"((r)[28]),"=r"((r)[29]),"=r"((r)[30]),"=r"((r)[31]) : "r"(a))
#endif  // HAS_TCGEN05

// ---------------------------------------------------------------------------
// Routing + gather
// ---------------------------------------------------------------------------
__global__ void route_kernel(const int* __restrict__ eidx) {
    __shared__ int s_cnt[NEXP], s_off[NEXP], s_cur[NEXP];
    int t = threadIdx.x;
    if (t < NEXP) s_cnt[t] = 0;
    __syncthreads();
    for (int p = t; p < NPAIR; p += blockDim.x) atomicAdd(&s_cnt[eidx[p]], 1);
    __syncthreads();
    if (t == 0) {
        int o = 0;
        for (int e = 0; e < NEXP; e++) { s_off[e] = o; s_cur[e] = o; o += s_cnt[e]; }
    }
    __syncthreads();
    for (int p = t; p < NPAIR; p += blockDim.x) {
        int pos = atomicAdd(&s_cur[eidx[p]], 1);
        d_tok[pos] = p >> 1;
        d_pos[p]   = pos;
    }
    if (t < NEXP) { d_cnt[t] = s_cnt[t]; d_off[t] = s_off[t]; }
}

__global__ __launch_bounds__(256)
void xgather_kernel(const float* __restrict__ x) {
    const int slot = blockIdx.x;
    uint32_t* dst = d_xg + (size_t)slot * (HIDDEN / 2);
    if (slot < NPAIR) {
        const float* src = x + (size_t)d_tok[slot] * HIDDEN;
        for (int i = threadIdx.x; i < HIDDEN / 8; i += 256) {
            float4 v0 = *(const float4*)(src + i * 8);
            float4 v1 = *(const float4*)(src + i * 8 + 4);
            *(uint4*)(dst + i * 4) = make_uint4(packh2(v0.x, v0.y), packh2(v0.z, v0.w),
                                                packh2(v1.x, v1.y), packh2(v1.z, v1.w));
        }
    } else {
        for (int i = threadIdx.x; i < HIDDEN / 8; i += 256)
            *(uint4*)(dst + i * 4) = make_uint4(0, 0, 0, 0);
    }
}

// ---------------------------------------------------------------------------
// GEMM1: 128 rows x N=64 per CTA; gate/up fused; h -> d_hbuf fp16
// TMEM: gate@0..63, up@64..127. 3 CTAs/SM.
// ---------------------------------------------------------------------------
__global__ __launch_bounds__(256, 3)
void gemm1_kernel(const float* __restrict__ w1g,
                  const float* __restrict__ w3g) {
    const int e    = blockIdx.x >> 5;
    const int cnt  = d_cnt[e];
    const int m0   = (blockIdx.x & 31) * BM;
    if (m0 >= cnt) return;
    const int n0   = blockIdx.y * BN1;
    const int off  = d_off[e];
    const int tid = threadIdx.x, wid = tid >> 5, lid = tid & 31;

    const float* w1b = w1g + (size_t)e * HIDDEN * INTER + n0;
    const float* w3b = w3g + (size_t)e * HIDDEN * INTER + n0;

#if HAS_TCGEN05
    extern __shared__ char smem[];
    const uint32_t sb = smem_u32(smem);

    if (wid == 0) TC_ALLOC(sb + SMEM_TMEM, 128);
    if (tid == 0)
        for (int s = 0; s < NSTG; s++) MBAR_INIT(sb + SMEM_CONS + 8 * s, 1);
    __syncthreads();
    uint32_t tmem;
    asm volatile("ld.shared.b32 %0, [%1];" : "=r"(tmem) : "r"(sb + SMEM_TMEM));
    if (wid == 0) TC_RELINQ();

    // A tasks (4): t = tid + i*256 -> m = t>>3 (0..127? 1024 tasks: t>>3 0..127)
    uint32_t xoff[4], a_sw[4];
#pragma unroll
    for (int i = 0; i < 4; i++) {
        int t = tid + i * 256, m = t >> 3, kb = t & 7;   // kb: 16B block in row
        xoff[i] = (uint32_t)(off + m0 + m) * (HIDDEN / 2) + kb * 4;
        a_sw[i] = swz128((uint32_t)(m * 128 + kb * 16));
    }
    // W tasks (2 per matrix): t -> n = t&63, kb = t>>6 (0..7)
    const float *w1t[2], *w3t[2]; uint32_t w_sw[2];
#pragma unroll
    for (int i = 0; i < 2; i++) {
        int t = tid + i * 256, n = t & 63, kb = t >> 6;
        w1t[i] = w1b + (size_t)(kb * 8) * INTER + n;
        w3t[i] = w3b + (size_t)(kb * 8) * INTER + n;
        w_sw[i] = swz128((uint32_t)(n * 128 + kb * 16));
    }

    uint32_t apf[16], w1pf[8], w3pf[8];
    auto prefetch = [&](int k0) {
        const int kw = k0 / 2;
#pragma unroll
        for (int i = 0; i < 4; i++) {
            uint4 v = *(const uint4*)(d_xg + xoff[i] + kw);
            apf[4*i] = v.x; apf[4*i+1] = v.y; apf[4*i+2] = v.z; apf[4*i+3] = v.w;
        }
#pragma unroll
        for (int i = 0; i < 2; i++) {
            const float* p1 = w1t[i] + (size_t)k0 * INTER;
            const float* p3 = w3t[i] + (size_t)k0 * INTER;
            float t1[8], t3[8];
#pragma unroll
            for (int j = 0; j < 8; j++) {
                t1[j] = p1[(size_t)j * INTER];
                t3[j] = p3[(size_t)j * INTER];
            }
#pragma unroll
            for (int j = 0; j < 4; j++) {
                w1pf[4*i+j] = packh2(t1[2*j], t1[2*j+1]);
                w3pf[4*i+j] = packh2(t3[2*j], t3[2*j+1]);
            }
        }
    };
    auto sts = [&](uint32_t stg) {
#pragma unroll
        for (int i = 0; i < 4; i++)
            STS128(stg + a_sw[i], apf[4*i], apf[4*i+1], apf[4*i+2], apf[4*i+3]);
#pragma unroll
        for (int i = 0; i < 2; i++) {
            STS128(stg + A_TILE_B + w_sw[i], w1pf[4*i], w1pf[4*i+1], w1pf[4*i+2], w1pf[4*i+3]);
            STS128(stg + A_TILE_B + W_TILE_B + w_sw[i], w3pf[4*i], w3pf[4*i+1], w3pf[4*i+2], w3pf[4*i+3]);
        }
    };

    prefetch(0);
    const int NC = HIDDEN / BK_TC;   // 32
    for (int c = 0; c < NC; c++) {
        const int s = c & 1;
        if (c >= NSTG) MBAR_WAIT(sb + SMEM_CONS + 8 * s, ((c >> 1) - 1) & 1);

        const uint32_t stg = sb + SMEM_DATA + s * G1_STAGE;
        sts(stg);
        __syncthreads();

        if (tid == 0) {
            FENCE_ASYNC();
            uint64_t ad = make_desc(stg);
            uint64_t b1 = make_desc(stg + A_TILE_B);
            uint64_t b3 = make_desc(stg + A_TILE_B + W_TILE_B);
#pragma unroll
            for (int ks = 0; ks < 4; ks++) {
                uint32_t en = (c > 0 || ks > 0) ? 1u : 0u;
                mma_f16_ss(tmem,      ad + ks * 2, b1 + ks * 2, IDESC_G1, en);
                mma_f16_ss(tmem + 64, ad + ks * 2, b3 + ks * 2, IDESC_G1, en);
            }
            TC_COMMIT(sb + SMEM_CONS + 8 * s);
        }
        if (c + 1 < NC) prefetch((c + 1) * BK_TC);
    }

    MBAR_WAIT(sb + SMEM_CONS + 8 * ((NC - 1) & 1), ((NC - 1) >> 1) & 1);
    TC_FENCE_AFTER();
    {
        // 8 warps: subpartition = wid&3 (rows), col-half h = wid>>2 (32 cols)
        const int h  = wid >> 2;
        const int mr = (wid & 3) * 32 + lid;
        const int r  = m0 + mr;
        const bool ok = r < cnt;
        uint32_t* hrow = d_hbuf + (size_t)(off + r) * (INTER / 2) + n0 / 2 + h * 16;
        uint32_t gr[32], ur[32];
        LDTM_X32(gr, tmem + h * 32);
        LDTM_X32(ur, tmem + 64 + h * 32);
        TC_WAIT_LD();
        if (ok) {
            uint32_t hw[16];
#pragma unroll
            for (int j = 0; j < 16; j++) {
                float g0 = __uint_as_float(gr[2*j]);
                float g1 = __uint_as_float(gr[2*j+1]);
                float h0 = g0 / (1.f + __expf(-g0)) * __uint_as_float(ur[2*j]);
                float h1 = g1 / (1.f + __expf(-g1)) * __uint_as_float(ur[2*j+1]);
                hw[j] = packh2(h0, h1);
            }
#pragma unroll
            for (int j = 0; j < 16; j += 4)
                *(uint4*)(hrow + j) = make_uint4(hw[j], hw[j+1], hw[j+2], hw[j+3]);
        }
    }
    __syncthreads();
    if (wid == 0) TC_DEALLOC(tmem, 128);

#else
    // ======= fallback: single-buffered mma.sync =======
    extern __shared__ uint32_t smw[];
    uint32_t* As  = smw;                 // 128 x FSTR
    uint32_t* W1s = As + 128 * FSTR;     // 64 x FSTR
    uint32_t* W3s = W1s + 64 * FSTR;
    const int g = lid >> 2, tg = lid & 3;
    const int rg = (wid >> 1) * 32, cg = (wid & 1) * 32;

    float gacc[2][4][4], uacc[2][4][4];
#pragma unroll
    for (int mi = 0; mi < 2; mi++)
#pragma unroll
        for (int ni = 0; ni < 4; ni++)
#pragma unroll
            for (int r = 0; r < 4; r++) { gacc[mi][ni][r] = 0.f; uacc[mi][ni][r] = 0.f; }

    for (int c = 0; c < HIDDEN / BK_TC; c++) {
        const int k0 = c * BK_TC;
#pragma unroll
        for (int i = 0; i < 4; i++) {
            int t = tid + i * 256, m = t >> 3, kb = t & 7;
            uint4 v = *(const uint4*)(d_xg + (size_t)(off + m0 + m) * (HIDDEN/2) + k0/2 + kb * 4);
            uint32_t* p = &As[m * FSTR + kb * 4];
            p[0] = v.x; p[1] = v.y; p[2] = v.z; p[3] = v.w;
        }
#pragma unroll
        for (int i = 0; i < 2; i++) {
            int t = tid + i * 256, n = t & 63, kp = t >> 6;
            const float* p1 = w1b + (size_t)(k0 + kp * 8) * INTER + n;
            const float* p3 = w3b + (size_t)(k0 + kp * 8) * INTER + n;
#pragma unroll
            for (int j = 0; j < 4; j++) {
                W1s[n * FSTR + kp * 4 + j] = packh2(p1[(2*j)*INTER], p1[(2*j+1)*INTER]);
                W3s[n * FSTR + kp * 4 + j] = packh2(p3[(2*j)*INTER], p3[(2*j+1)*INTER]);
            }
        }
        __syncthreads();
#pragma unroll
        for (int kk = 0; kk < 4; kk++) {
            const int ko = kk * 8;
            uint32_t a[2][4];
#pragma unroll
            for (int mi = 0; mi < 2; mi++) {
                int rb = rg + mi * 16;
                a[mi][0] = As[(rb + g)     * FSTR + ko + tg];
                a[mi][1] = As[(rb + g + 8) * FSTR + ko + tg];
                a[mi][2] = As[(rb + g)     * FSTR + ko + tg + 4];
                a[mi][3] = As[(rb + g + 8) * FSTR + ko + tg + 4];
            }
#pragma unroll
            for (int ni = 0; ni < 4; ni++) {
                int cb = cg + ni * 8;
                uint32_t b0 = W1s[(cb + g) * FSTR + ko + tg];
                uint32_t b1 = W1s[(cb + g) * FSTR + ko + tg + 4];
                uint32_t c0 = W3s[(cb + g) * FSTR + ko + tg];
                uint32_t c1 = W3s[(cb + g) * FSTR + ko + tg + 4];
                mma16816(gacc[0][ni], a[0], b0, b1);
                mma16816(gacc[1][ni], a[1], b0, b1);
                mma16816(uacc[0][ni], a[0], c0, c1);
                mma16816(uacc[1][ni], a[1], c0, c1);
            }
        }
        __syncthreads();
    }
#pragma unroll
    for (int mi = 0; mi < 2; mi++)
#pragma unroll
        for (int ni = 0; ni < 4; ni++) {
            int r0 = m0 + rg + mi * 16 + g;
            int r1 = r0 + 8;
            int col = n0 + cg + ni * 8 + tg * 2;
            if (r0 < cnt) {
                float g0 = gacc[mi][ni][0], g1 = gacc[mi][ni][1];
                float h0 = g0 / (1.f + __expf(-g0)) * uacc[mi][ni][0];
                float h1 = g1 / (1.f + __expf(-g1)) * uacc[mi][ni][1];
                d_hbuf[((size_t)(off + r0) * INTER + col) >> 1] = packh2(h0, h1);
            }
            if (r1 < cnt) {
                float g2 = gacc[mi][ni][2], g3 = gacc[mi][ni][3];
                float h2 = g2 / (1.f + __expf(-g2)) * uacc[mi][ni][2];
                float h3 = g3 / (1.f + __expf(-g3)) * uacc[mi][ni][3];
                d_hbuf[((size_t)(off + r1) * INTER + col) >> 1] = packh2(h2, h3);
            }
        }
#endif
}

// ---------------------------------------------------------------------------
// GEMM2: 128 rows x N=64 per CTA; y -> d_ybuf. TMEM: y@0..63. 3 CTAs/SM.
// ---------------------------------------------------------------------------
__global__ __launch_bounds__(256, 3)
void gemm2_kernel(const float* __restrict__ w2g) {
    const int e    = blockIdx.x >> 5;
    const int cnt  = d_cnt[e];
    const int m0   = (blockIdx.x & 31) * BM;
    if (m0 >= cnt) return;
    const int n0   = blockIdx.y * BN2;
    const int off  = d_off[e];
    const int tid = threadIdx.x, wid = tid >> 5, lid = tid & 31;

    const float* w2b = w2g + (size_t)e * INTER * HIDDEN + n0;

#if HAS_TCGEN05
    extern __shared__ char smem[];
    const uint32_t sb = smem_u32(smem);

    if (wid == 0) TC_ALLOC(sb + SMEM_TMEM, 64);
    if (tid == 0)
        for (int s = 0; s < NSTG; s++) MBAR_INIT(sb + SMEM_CONS + 8 * s, 1);
    __syncthreads();
    uint32_t tmem;
    asm volatile("ld.shared.b32 %0, [%1];" : "=r"(tmem) : "r"(sb + SMEM_TMEM));
    if (wid == 0) TC_RELINQ();

    uint32_t hoff[4], a_sw[4];
#pragma unroll
    for (int i = 0; i < 4; i++) {
        int t = tid + i * 256, m = t >> 3, kb = t & 7;
        hoff[i] = (uint32_t)(off + m0 + m) * (INTER / 2) + kb * 4;
        a_sw[i] = swz128((uint32_t)(m * 128 + kb * 16));
    }
    const float* w2t[2]; uint32_t w_sw[2];
#pragma unroll
    for (int i = 0; i < 2; i++) {
        int t = tid + i * 256, n = t & 63, kb = t >> 6;
        w2t[i] = w2b + (size_t)(kb * 8) * HIDDEN + n;
        w_sw[i] = swz128((uint32_t)(n * 128 + kb * 16));
    }

    uint32_t apf[16], wpf[8];
    auto prefetch = [&](int c) {
#pragma unroll
        for (int i = 0; i < 4; i++) {
            uint4 v = *(const uint4*)(d_hbuf + hoff[i] + (size_t)c * 32);
            apf[4*i] = v.x; apf[4*i+1] = v.y; apf[4*i+2] = v.z; apf[4*i+3] = v.w;
        }
        const int k0 = c * BK_TC;
#pragma unroll
        for (int i = 0; i < 2; i++) {
            const float* p = w2t[i] + (size_t)k0 * HIDDEN;
            float t2[8];
#pragma unroll
            for (int j = 0; j < 8; j++) t2[j] = p[(size_t)j * HIDDEN];
#pragma unroll
            for (int j = 0; j < 4; j++) wpf[4*i+j] = packh2(t2[2*j], t2[2*j+1]);
        }
    };
    auto sts = [&](uint32_t stg) {
#pragma unroll
        for (int i = 0; i < 4; i++)
            STS128(stg + a_sw[i], apf[4*i], apf[4*i+1], apf[4*i+2], apf[4*i+3]);
#pragma unroll
        for (int i = 0; i < 2; i++)
            STS128(stg + A_TILE_B + w_sw[i], wpf[4*i], wpf[4*i+1], wpf[4*i+2], wpf[4*i+3]);
    };

    prefetch(0);
    const int NC = INTER / BK_TC;   // 88
    for (int c = 0; c < NC; c++) {
        const int s = c & 1;
        if (c >= NSTG) MBAR_WAIT(sb + SMEM_CONS + 8 * s, ((c >> 1) - 1) & 1);

        const uint32_t stg = sb + SMEM_DATA + s * G2_STAGE;
        sts(stg);
        __syncthreads();

        if (tid == 0) {
            FENCE_ASYNC();
            uint64_t ad = make_desc(stg);
            uint64_t bd = make_desc(stg + A_TILE_B);
#pragma unroll
            for (int ks = 0; ks < 4; ks++)
                mma_f16_ss(tmem, ad + ks * 2, bd + ks * 2, IDESC_G2,
                           (c > 0 || ks > 0) ? 1u : 0u);
            TC_COMMIT(sb + SMEM_CONS + 8 * s);
        }
        if (c + 1 < NC) prefetch(c + 1);
    }

    MBAR_WAIT(sb + SMEM_CONS + 8 * ((NC - 1) & 1), ((NC - 1) >> 1) & 1);
    TC_FENCE_AFTER();
    {
        const int h  = wid >> 2;                  // col half (32 cols)
        const int mr = (wid & 3) * 32 + lid;
        const int r  = m0 + mr;
        const bool ok = r < cnt;
        float* yrow = d_ybuf + (size_t)(off + r) * HIDDEN + n0 + h * 32;
        uint32_t yr[32];
        LDTM_X32(yr, tmem + h * 32);
        TC_WAIT_LD();
        if (ok) {
#pragma unroll
            for (int j = 0; j < 32; j += 4) {
                float4 v;
                v.x = __uint_as_float(yr[j]);   v.y = __uint_as_float(yr[j+1]);
                v.z = __uint_as_float(yr[j+2]); v.w = __uint_as_float(yr[j+3]);
                *(float4*)(yrow + j) = v;
            }
        }
    }
    __syncthreads();
    if (wid == 0) TC_DEALLOC(tmem, 64);

#else
    // ======= fallback: single-buffered mma.sync =======
    extern __shared__ uint32_t smw[];
    uint32_t* As = smw;               // 128 x FSTR
    uint32_t* Ws = As + 128 * FSTR;   // 64 x FSTR
    const int g = lid >> 2, tg = lid & 3;
    const int rg = (wid >> 1) * 32, cg = (wid & 1) * 32;

    float acc[2][4][4];
#pragma unroll
    for (int mi = 0; mi < 2; mi++)
#pragma unroll
        for (int ni = 0; ni < 4; ni++)
#pragma unroll
            for (int r = 0; r < 4; r++) acc[mi][ni][r] = 0.f;

    for (int c = 0; c < INTER / BK_TC; c++) {
        const int k0 = c * BK_TC;
#pragma unroll
        for (int i = 0; i < 4; i++) {
            int t = tid + i * 256, m = t >> 3, kb = t & 7;
            uint4 v = *(const uint4*)(d_hbuf + (size_t)(off + m0 + m) * (INTER/2) + k0/2 + kb * 4);
            uint32_t* p = &As[m * FSTR + kb * 4];
            p[0] = v.x; p[1] = v.y; p[2] = v.z; p[3] = v.w;
        }
#pragma unroll
        for (int i = 0; i < 2; i++) {
            int t = tid + i * 256, n = t & 63, kp = t >> 6;
            const float* p = w2b + (size_t)(k0 + kp * 8) * HIDDEN + n;
#pragma unroll
            for (int j = 0; j < 4; j++)
                Ws[n * FSTR + kp * 4 + j] = packh2(p[(2*j)*HIDDEN], p[(2*j+1)*HIDDEN]);
        }
        __syncthreads();
#pragma unroll
        for (int kk = 0; kk < 4; kk++) {
            const int ko = kk * 8;
            uint32_t a[2][4];
#pragma unroll
            for (int mi = 0; mi < 2; mi++) {
                int rb = rg + mi * 16;
                a[mi][0] = As[(rb + g)     * FSTR + ko + tg];
                a[mi][1] = As[(rb + g + 8) * FSTR + ko + tg];
                a[mi][2] = As[(rb + g)     * FSTR + ko + tg + 4];
                a[mi][3] = As[(rb + g + 8) * FSTR + ko + tg + 4];
            }
#pragma unroll
            for (int ni = 0; ni < 4; ni++) {
                int cb = cg + ni * 8;
                uint32_t b0 = Ws[(cb + g) * FSTR + ko + tg];
                uint32_t b1 = Ws[(cb + g) * FSTR + ko + tg + 4];
                mma16816(acc[0][ni], a[0], b0, b1);
                mma16816(acc[1][ni], a[1], b0, b1);
            }
        }
        __syncthreads();
    }
#pragma unroll
    for (int mi = 0; mi < 2; mi++)
#pragma unroll
        for (int ni = 0; ni < 4; ni++) {
            int r0 = m0 + rg + mi * 16 + g;
            int r1 = r0 + 8;
            int col = n0 + cg + ni * 8 + tg * 2;
            if (r0 < cnt)
                *(float2*)(d_ybuf + (size_t)(off + r0) * HIDDEN + col) =
                    make_float2(acc[mi][ni][0], acc[mi][ni][1]);
            if (r1 < cnt)
                *(float2*)(d_ybuf + (size_t)(off + r1) * HIDDEN + col) =
                    make_float2(acc[mi][ni][2], acc[mi][ni][3]);
        }
#endif
}

// ---------------------------------------------------------------------------
// Combine
// ---------------------------------------------------------------------------
__global__ __launch_bounds__(256)
void combine_kernel(const float* __restrict__ ew, float* __restrict__ out) {
    const int t = blockIdx.x;
    const int p0 = d_pos[2 * t], p1 = d_pos[2 * t + 1];
    const float w0 = ew[2 * t], w1 = ew[2 * t + 1];
    const float4* y0 = (const float4*)(d_ybuf + (size_t)p0 * HIDDEN);
    const float4* y1 = (const float4*)(d_ybuf + (size_t)p1 * HIDDEN);
    float4* o = (float4*)(out + (size_t)t * HIDDEN);
#pragma unroll
    for (int i = threadIdx.x; i < HIDDEN / 4; i += 256) {
        float4 a = y0[i], b = y1[i], r;
        r.x = w0 * a.x + w1 * b.x; r.y = w0 * a.y + w1 * b.y;
        r.z = w0 * a.z + w1 * b.z; r.w = w0 * a.w + w1 * b.w;
        o[i] = r;
    }
}

// ---------------------------------------------------------------------------
// launch — inputs: x, expert_weights, w1, w2, w3, expert_indices
// ---------------------------------------------------------------------------
extern "C" void kernel_launch(void* const* d_in, const int* in_sizes, int n_in,
                              void* d_out, int out_size) {
    const float* x  = (const float*)d_in[0];
    const float* ew = (const float*)d_in[1];
    const float* w1 = (const float*)d_in[2];
    const float* w2 = (const float*)d_in[3];
    const float* w3 = (const float*)d_in[4];
    const int*   ei = (const int*)d_in[5];
    float* out = (float*)d_out;

    static int attr_done = 0;
    if (!attr_done) {
        cudaFuncSetAttribute(gemm1_kernel, cudaFuncAttributeMaxDynamicSharedMemorySize, G1_SMEM);
        cudaFuncSetAttribute(gemm2_kernel, cudaFuncAttributeMaxDynamicSharedMemorySize, G2_SMEM);
        attr_done = 1;
    }

    route_kernel<<<1, 256>>>(ei);
    xgather_kernel<<<NPAIR + 256, 256>>>(x);

    dim3 g1(NEXP * MAXMT, INTER / BN1);   // 256 x 88
    gemm1_kernel<<<g1, 256, G1_SMEM>>>(w1, w3);

    dim3 g2(NEXP * MAXMT, HIDDEN / BN2);  // 256 x 32
    gemm2_kernel<<<g2, 256, G2_SMEM>>>(w2);

    combine_kernel<<<TOKENS, 256>>>(ew, out);
}

// round 15
// speedup vs baseline: 1.3406x; 1.3406x over previous
#include <cuda_runtime.h>
#include <cuda_fp16.h>
#include <cstdint>

// Problem constants
#define TOKENS 2048
#define HIDDEN 2048
#define INTER  5632
#define NEXP   8
#define TOPK   2
#define NPAIR  4096

#define MPAIR  16          // m-pair slots per expert (2x128 rows each)
#define BN1    64          // gemm1 n-tile
#define BN2    128         // gemm2 n-tile

// ---- tcgen05 config: fp16 K-major SW128, BK=64, NSTG=2, 2 CTAs/SM ----
#define BK_TC 64
#define NSTG  2
#define A_TILE_B  (256 * 128)            // 256 rows x 64k fp16 = 32 KB
#define W1_TILE_B (64 * 128)             // 8 KB
#define W2_TILE_B (128 * 128)            // 16 KB
#define G1_STAGE  (A_TILE_B + 2 * W1_TILE_B)   // 48 KB
#define G2_STAGE  (A_TILE_B + W2_TILE_B)       // 48 KB
#define SMEM_TMEM 0
#define SMEM_CONS 16
#define SMEM_DATA 1024
#define G1_SMEM (SMEM_DATA + NSTG * G1_STAGE)  // 99,328 -> 2 CTAs/SM
#define G2_SMEM (SMEM_DATA + NSTG * G2_STAGE)  // 99,328 -> 2 CTAs/SM

#define IDESC_G1 ((1u << 4) | ((BN1 / 8) << 17) | (8u << 24))   // M=128,N=64
#define IDESC_G2 ((1u << 4) | ((BN2 / 8) << 17) | (8u << 24))   // M=128,N=128

#define FSTR 36   // fallback smem stride

#if defined(__CUDA_ARCH__) && defined(__CUDA_ARCH_FEAT_SM103_ALL)
#define HAS_TCGEN05 1
#else
#define HAS_TCGEN05 0
#endif

// -------- persistent device scratch --------
__device__ int      d_cnt[NEXP];
__device__ int      d_off[NEXP];
__device__ int      d_tok[NPAIR];
__device__ float    d_wgt[NPAIR];
__device__ uint32_t d_xg[(size_t)(NPAIR + 256) * (HIDDEN / 2)];   // sorted x fp16 + pad
__device__ uint32_t d_hbuf[(size_t)(NPAIR + 256) * (INTER / 2)];  // h fp16, padded

// ---------------------------------------------------------------------------
// helpers
// ---------------------------------------------------------------------------
__device__ __forceinline__ uint32_t packh2(float lo, float hi) {
    __half2 h = __floats2half2_rn(lo, hi);
    return *reinterpret_cast<uint32_t*>(&h);
}
__device__ __forceinline__ void mma16816(float c[4], const uint32_t a[4],
                                         uint32_t b0, uint32_t b1) {
    asm volatile(
        "mma.sync.aligned.m16n8k16.row.col.f32.f16.f16.f32 "
        "{%0,%1,%2,%3}, {%4,%5,%6,%7}, {%8,%9}, {%0,%1,%2,%3};\n"
        : "+f"(c[0]), "+f"(c[1]), "+f"(c[2]), "+f"(c[3])
        : "r"(a[0]), "r"(a[1]), "r"(a[2]), "r"(a[3]), "r"(b0), "r"(b1));
}
#define STS128(a, q0, q1, q2, q3)                                                 \
    asm volatile("st.shared.v4.b32 [%0], {%1,%2,%3,%4};"                          \
        :: "r"(a), "r"(q0), "r"(q1), "r"(q2), "r"(q3) : "memory")

#if HAS_TCGEN05
__device__ __forceinline__ uint32_t smem_u32(const void* p) {
    uint32_t a;
    asm("{ .reg .u64 t; cvta.to.shared.u64 t, %1; cvt.u32.u64 %0, t; }" : "=r"(a) : "l"(p));
    return a;
}
__device__ __forceinline__ uint32_t swz128(uint32_t b) { return b ^ ((b >> 3) & 0x70); }
static __device__ __forceinline__ uint64_t make_desc(uint32_t addr) {
    // K-major SW128: layout=2, version=1, SBO=64, LBO=1
    return ((uint64_t)2 << 61) | ((uint64_t)1 << 46) | ((uint64_t)64 << 32) |
           ((uint64_t)1 << 16) | ((uint64_t)(addr >> 4) & 0x3FFF);
}

#define MBAR_INIT(a, c) \
    asm volatile("mbarrier.init.shared.b64 [%0], %1;" :: "r"(a), "r"(c) : "memory")
#define MBAR_WAIT(a, ph) do {                                                     \
    uint32_t _m = (a), _p = (ph), _d;                                             \
    asm volatile("{\n\t.reg .pred p;\n\t"                                         \
        "mbarrier.try_wait.parity.acquire.cta.shared::cta.b64 p, [%1], %2;\n\t"   \
        "selp.b32 %0, 1, 0, p;\n\t}" : "=r"(_d) : "r"(_m), "r"(_p) : "memory");   \
    if (!_d) {                                                                     \
        asm volatile("{\n\t.reg .pred P1;\n\t"                                    \
        "W%=:\n\t"                                                                \
        "mbarrier.try_wait.parity.acquire.cta.shared::cta.b64 P1, [%0], %1, 0x989680;\n\t" \
        "@P1 bra.uni D%=;\n\t bra.uni W%=;\n\t D%=:\n\t}"                        \
        :: "r"(_m), "r"(_p) : "memory");                                          \
    } } while (0)

#define TC_ALLOC(sa, n)  asm volatile("tcgen05.alloc.cta_group::1.sync.aligned.shared::cta.b32 [%0], %1;" :: "r"(sa), "r"(n) : "memory")
#define TC_DEALLOC(t, n) asm volatile("tcgen05.dealloc.cta_group::1.sync.aligned.b32 %0, %1;" :: "r"(t), "r"(n))
#define TC_RELINQ()      asm volatile("tcgen05.relinquish_alloc_permit.cta_group::1.sync.aligned;")
#define TC_COMMIT(a)     asm volatile("tcgen05.commit.cta_group::1.mbarrier::arrive::one.shared::cluster.b64 [%0];" :: "r"(a) : "memory")
#define TC_FENCE_AFTER() asm volatile("tcgen05.fence::after_thread_sync;" ::: "memory")
#define TC_WAIT_LD()     asm volatile("tcgen05.wait::ld.sync.aligned;" ::: "memory")
#define FENCE_ASYNC()    asm volatile("fence.proxy.async.shared::cta;" ::: "memory")

__device__ __forceinline__ void mma_f16_ss(uint32_t d, uint64_t ad, uint64_t bd,
                                           uint32_t idesc, uint32_t en) {
    asm volatile(
        "{\n\t.reg .pred p;\n\t"
        "setp.ne.u32 p, %4, 0;\n\t"
        "tcgen05.mma.cta_group::1.kind::f16 [%0], %1, %2, %3, {%5, %5, %5, %5}, p;\n\t"
        "}" :: "r"(d), "l"(ad), "l"(bd), "r"(idesc), "r"(en), "r"(0u) : "memory");
}

#define LDTM_X32(r, a)                                                            \
    asm volatile("tcgen05.ld.sync.aligned.32x32b.x32.b32 "                        \
        "{%0,%1,%2,%3,%4,%5,%6,%7,%8,%9,%10,%11,%12,%13,%14,%15,"                 \
        "%16,%17,%18,%19,%20,%21,%22,%23,%24,%25,%26,%27,%28,%29,%30,%31}, [%32];"\
        : "=r"((r)[0]),"=r"((r)[1]),"=r"((r)[2]),"=r"((r)[3]),                    \
          "=r"((r)[4]),"=r"((r)[5]),"=r"((r)[6]),"=r"((r)[7]),                    \
          "=r"((r)[8]),"=r"((r)[9]),"=r"((r)[10]),"=r"((r)[11]),                  \
          "=r"((r)[12]),"=r"((r)[13]),"=r"((r)[14]),"=r"((r)[15]),                \
          "=r"((r)[16]),"=r"((r)[17]),"=r"((r)[18]),"=r"((r)[19]),                \
          "=r"((r)[20]),"=r"((r)[21]),"=r"((r)[22]),"=r"((r)[23]),                \
          "=r"((r)[24]),"=r"((r)[25]),"=r"((r)[26]),"=r"((r)[27]),                \
          "=r"((r)[28]),"=r"((r)[29]),"=r"((r)[30]),"=r"((r)[31]) : "r"(a))
#endif  // HAS_TCGEN05

// ---------------------------------------------------------------------------
// Routing (+ per-slot router weight) and gather
// ---------------------------------------------------------------------------
__global__ void route_kernel(const int* __restrict__ eidx,
                             const float* __restrict__ ew) {
    __shared__ int s_cnt[NEXP], s_off[NEXP], s_cur[NEXP];
    int t = threadIdx.x;
    if (t < NEXP) s_cnt[t] = 0;
    __syncthreads();
    for (int p = t; p < NPAIR; p += blockDim.x) atomicAdd(&s_cnt[eidx[p]], 1);
    __syncthreads();
    if (t == 0) {
        int o = 0;
        for (int e = 0; e < NEXP; e++) { s_off[e] = o; s_cur[e] = o; o += s_cnt[e]; }
    }
    __syncthreads();
    for (int p = t; p < NPAIR; p += blockDim.x) {
        int pos = atomicAdd(&s_cur[eidx[p]], 1);
        d_tok[pos] = p >> 1;
        d_wgt[pos] = ew[p];
    }
    if (t < NEXP) { d_cnt[t] = s_cnt[t]; d_off[t] = s_off[t]; }
}

__global__ __launch_bounds__(256)
void xgather_kernel(const float* __restrict__ x) {
    const int slot = blockIdx.x;
    uint32_t* dst = d_xg + (size_t)slot * (HIDDEN / 2);
    if (slot < NPAIR) {
        const float* src = x + (size_t)d_tok[slot] * HIDDEN;
        for (int i = threadIdx.x; i < HIDDEN / 8; i += 256) {
            float4 v0 = *(const float4*)(src + i * 8);
            float4 v1 = *(const float4*)(src + i * 8 + 4);
            *(uint4*)(dst + i * 4) = make_uint4(packh2(v0.x, v0.y), packh2(v0.z, v0.w),
                                                packh2(v1.x, v1.y), packh2(v1.z, v1.w));
        }
    } else {
        for (int i = threadIdx.x; i < HIDDEN / 8; i += 256)
            *(uint4*)(dst + i * 4) = make_uint4(0, 0, 0, 0);
    }
}

// ---------------------------------------------------------------------------
// GEMM1: per CTA: 2 m-tiles (256 rows) x N=64; gate/up fused; h -> d_hbuf fp16
// TMEM: gate0@0, up0@64, gate1@128, up1@192.
// ---------------------------------------------------------------------------
__global__ __launch_bounds__(256, 2)
void gemm1_kernel(const float* __restrict__ w1g,
                  const float* __restrict__ w3g) {
    const int e    = blockIdx.x >> 4;
    const int cnt  = d_cnt[e];
    const int m0   = (blockIdx.x & 15) * 256;
    if (m0 >= cnt) return;
    const int n0   = blockIdx.y * BN1;
    const int off  = d_off[e];
    const int tid = threadIdx.x, wid = tid >> 5, lid = tid & 31;

    const float* w1b = w1g + (size_t)e * HIDDEN * INTER + n0;
    const float* w3b = w3g + (size_t)e * HIDDEN * INTER + n0;

#if HAS_TCGEN05
    extern __shared__ char smem[];
    const uint32_t sb = smem_u32(smem);

    if (wid == 0) TC_ALLOC(sb + SMEM_TMEM, 256);
    if (tid == 0)
        for (int s = 0; s < NSTG; s++) MBAR_INIT(sb + SMEM_CONS + 8 * s, 1);
    __syncthreads();
    uint32_t tmem;
    asm volatile("ld.shared.b32 %0, [%1];" : "=r"(tmem) : "r"(sb + SMEM_TMEM));
    if (wid == 0) TC_RELINQ();

    // A tasks (8): t = tid + i*256 -> m = t>>3 (0..255), kb = t&7 (16B block)
    uint32_t xoff[8], a_sw[8];
#pragma unroll
    for (int i = 0; i < 8; i++) {
        int t = tid + i * 256, m = t >> 3, kb = t & 7;
        xoff[i] = (uint32_t)(off + m0 + m) * (HIDDEN / 2) + kb * 4;
        a_sw[i] = swz128((uint32_t)(m * 128 + kb * 16));
    }
    // W tasks (2 per matrix): t -> n = t&63, kb = t>>6 (0..7)
    const float *w1t[2], *w3t[2]; uint32_t w_sw[2];
#pragma unroll
    for (int i = 0; i < 2; i++) {
        int t = tid + i * 256, n = t & 63, kb = t >> 6;
        w1t[i] = w1b + (size_t)(kb * 8) * INTER + n;
        w3t[i] = w3b + (size_t)(kb * 8) * INTER + n;
        w_sw[i] = swz128((uint32_t)(n * 128 + kb * 16));
    }

    uint32_t apf[32], w1pf[8], w3pf[8];
    auto prefetch = [&](int k0) {
        const int kw = k0 / 2;
#pragma unroll
        for (int i = 0; i < 8; i++) {
            uint4 v = *(const uint4*)(d_xg + xoff[i] + kw);
            apf[4*i] = v.x; apf[4*i+1] = v.y; apf[4*i+2] = v.z; apf[4*i+3] = v.w;
        }
#pragma unroll
        for (int i = 0; i < 2; i++) {
            const float* p1 = w1t[i] + (size_t)k0 * INTER;
            const float* p3 = w3t[i] + (size_t)k0 * INTER;
            float t1[8], t3[8];
#pragma unroll
            for (int j = 0; j < 8; j++) {
                t1[j] = p1[(size_t)j * INTER];
                t3[j] = p3[(size_t)j * INTER];
            }
#pragma unroll
            for (int j = 0; j < 4; j++) {
                w1pf[4*i+j] = packh2(t1[2*j], t1[2*j+1]);
                w3pf[4*i+j] = packh2(t3[2*j], t3[2*j+1]);
            }
        }
    };

    prefetch(0);
    const int NC = HIDDEN / BK_TC;   // 32
    for (int c = 0; c < NC; c++) {
        const int s = c & 1;
        if (c >= NSTG) MBAR_WAIT(sb + SMEM_CONS + 8 * s, ((c >> 1) - 1) & 1);

        const uint32_t stg = sb + SMEM_DATA + s * G1_STAGE;
#pragma unroll
        for (int i = 0; i < 8; i++)
            STS128(stg + a_sw[i], apf[4*i], apf[4*i+1], apf[4*i+2], apf[4*i+3]);
#pragma unroll
        for (int i = 0; i < 2; i++) {
            STS128(stg + A_TILE_B + w_sw[i], w1pf[4*i], w1pf[4*i+1], w1pf[4*i+2], w1pf[4*i+3]);
            STS128(stg + A_TILE_B + W1_TILE_B + w_sw[i], w3pf[4*i], w3pf[4*i+1], w3pf[4*i+2], w3pf[4*i+3]);
        }
        __syncthreads();

        if (tid == 0) {
            FENCE_ASYNC();
            uint64_t b1 = make_desc(stg + A_TILE_B);
            uint64_t b3 = make_desc(stg + A_TILE_B + W1_TILE_B);
#pragma unroll
            for (int mt = 0; mt < 2; mt++) {
                uint64_t ad = make_desc(stg + mt * (128 * 128));
#pragma unroll
                for (int ks = 0; ks < 4; ks++) {
                    uint32_t en = (c > 0 || ks > 0) ? 1u : 0u;
                    mma_f16_ss(tmem + mt * 128,      ad + ks * 2, b1 + ks * 2, IDESC_G1, en);
                    mma_f16_ss(tmem + mt * 128 + 64, ad + ks * 2, b3 + ks * 2, IDESC_G1, en);
                }
            }
            TC_COMMIT(sb + SMEM_CONS + 8 * s);
        }
        if (c + 1 < NC) prefetch((c + 1) * BK_TC);
    }

    MBAR_WAIT(sb + SMEM_CONS + 8 * ((NC - 1) & 1), ((NC - 1) >> 1) & 1);
    TC_FENCE_AFTER();
    {
        // warps 0-3: m-tile 0, warps 4-7: m-tile 1; subpartition = wid&3
        const int mt = wid >> 2;
        const int mr = (wid & 3) * 32 + lid;
        const int r  = m0 + mt * 128 + mr;
        const bool ok = r < cnt;
        uint32_t* hrow = d_hbuf + (size_t)(off + r) * (INTER / 2) + n0 / 2;
        const uint32_t tb = tmem + mt * 128;
#pragma unroll
        for (int cc = 0; cc < 2; cc++) {
            const int cb = cc * 32;
            uint32_t gr[32], ur[32];
            LDTM_X32(gr, tb + cb);
            LDTM_X32(ur, tb + 64 + cb);
            TC_WAIT_LD();
            if (ok) {
                uint32_t hw[16];
#pragma unroll
                for (int j = 0; j < 16; j++) {
                    float g0 = __uint_as_float(gr[2*j]);
                    float g1 = __uint_as_float(gr[2*j+1]);
                    float h0 = g0 / (1.f + __expf(-g0)) * __uint_as_float(ur[2*j]);
                    float h1 = g1 / (1.f + __expf(-g1)) * __uint_as_float(ur[2*j+1]);
                    hw[j] = packh2(h0, h1);
                }
#pragma unroll
                for (int j = 0; j < 16; j += 4)
                    *(uint4*)(hrow + cb/2 + j) = make_uint4(hw[j], hw[j+1], hw[j+2], hw[j+3]);
            }
        }
    }
    __syncthreads();
    if (wid == 0) TC_DEALLOC(tmem, 256);

#else
    // ======= fallback: single-buffered mma.sync, 2 m-tiles sequential =======
    extern __shared__ uint32_t smw[];
    uint32_t* As  = smw;
    uint32_t* W1s = As + 128 * FSTR;
    uint32_t* W3s = W1s + 64 * FSTR;
    const int g = lid >> 2, tg = lid & 3;
    const int rg = (wid >> 1) * 32, cg = (wid & 1) * 32;

    for (int mt = 0; mt < 2; mt++) {
        const int mb = m0 + mt * 128;
        if (mb >= cnt) break;
        float gacc[2][4][4], uacc[2][4][4];
#pragma unroll
        for (int mi = 0; mi < 2; mi++)
#pragma unroll
            for (int ni = 0; ni < 4; ni++)
#pragma unroll
                for (int r = 0; r < 4; r++) { gacc[mi][ni][r] = 0.f; uacc[mi][ni][r] = 0.f; }

        for (int c = 0; c < HIDDEN / BK_TC; c++) {
            const int k0 = c * BK_TC;
#pragma unroll
            for (int i = 0; i < 2; i++) {
                int t = tid + i * 256, m = t >> 3, kb = t & 7;
                uint4 v = *(const uint4*)(d_xg + (size_t)(off + mb + m) * (HIDDEN/2) + k0/2 + kb * 4);
                uint32_t* p = &As[m * FSTR + kb * 4];
                p[0] = v.x; p[1] = v.y; p[2] = v.z; p[3] = v.w;
            }
#pragma unroll
            for (int i = 0; i < 2; i++) {
                int t = tid + i * 256, n = t & 63, kp = t >> 6;
                const float* p1 = w1b + (size_t)(k0 + kp * 8) * INTER + n;
                const float* p3 = w3b + (size_t)(k0 + kp * 8) * INTER + n;
#pragma unroll
                for (int j = 0; j < 4; j++) {
                    W1s[n * FSTR + kp * 4 + j] = packh2(p1[(2*j)*INTER], p1[(2*j+1)*INTER]);
                    W3s[n * FSTR + kp * 4 + j] = packh2(p3[(2*j)*INTER], p3[(2*j+1)*INTER]);
                }
            }
            __syncthreads();
#pragma unroll
            for (int kk = 0; kk < 4; kk++) {
                const int ko = kk * 8;
                uint32_t a[2][4];
#pragma unroll
                for (int mi = 0; mi < 2; mi++) {
                    int rb = rg + mi * 16;
                    a[mi][0] = As[(rb + g)     * FSTR + ko + tg];
                    a[mi][1] = As[(rb + g + 8) * FSTR + ko + tg];
                    a[mi][2] = As[(rb + g)     * FSTR + ko + tg + 4];
                    a[mi][3] = As[(rb + g + 8) * FSTR + ko + tg + 4];
                }
#pragma unroll
                for (int ni = 0; ni < 4; ni++) {
                    int cb = cg + ni * 8;
                    uint32_t b0 = W1s[(cb + g) * FSTR + ko + tg];
                    uint32_t b1 = W1s[(cb + g) * FSTR + ko + tg + 4];
                    uint32_t c0 = W3s[(cb + g) * FSTR + ko + tg];
                    uint32_t c1 = W3s[(cb + g) * FSTR + ko + tg + 4];
                    mma16816(gacc[0][ni], a[0], b0, b1);
                    mma16816(gacc[1][ni], a[1], b0, b1);
                    mma16816(uacc[0][ni], a[0], c0, c1);
                    mma16816(uacc[1][ni], a[1], c0, c1);
                }
            }
            __syncthreads();
        }
#pragma unroll
        for (int mi = 0; mi < 2; mi++)
#pragma unroll
            for (int ni = 0; ni < 4; ni++) {
                int r0 = mb + rg + mi * 16 + g;
                int r1 = r0 + 8;
                int col = n0 + cg + ni * 8 + tg * 2;
                if (r0 < cnt) {
                    float g0 = gacc[mi][ni][0], g1 = gacc[mi][ni][1];
                    float h0 = g0 / (1.f + __expf(-g0)) * uacc[mi][ni][0];
                    float h1 = g1 / (1.f + __expf(-g1)) * uacc[mi][ni][1];
                    d_hbuf[((size_t)(off + r0) * INTER + col) >> 1] = packh2(h0, h1);
                }
                if (r1 < cnt) {
                    float g2 = gacc[mi][ni][2], g3 = gacc[mi][ni][3];
                    float h2 = g2 / (1.f + __expf(-g2)) * uacc[mi][ni][2];
                    float h3 = g3 / (1.f + __expf(-g3)) * uacc[mi][ni][3];
                    d_hbuf[((size_t)(off + r1) * INTER + col) >> 1] = packh2(h2, h3);
                }
            }
        __syncthreads();
    }
#endif
}

// ---------------------------------------------------------------------------
// GEMM2: per CTA: 2 m-tiles (256 rows) x N=128; weighted atomic scatter -> out
// TMEM: y0@0, y1@128.
// ---------------------------------------------------------------------------
__global__ __launch_bounds__(256, 2)
void gemm2_kernel(const float* __restrict__ w2g, float* __restrict__ out) {
    const int e    = blockIdx.x >> 4;
    const int cnt  = d_cnt[e];
    const int m0   = (blockIdx.x & 15) * 256;
    if (m0 >= cnt) return;
    const int n0   = blockIdx.y * BN2;
    const int off  = d_off[e];
    const int tid = threadIdx.x, wid = tid >> 5, lid = tid & 31;

    const float* w2b = w2g + (size_t)e * INTER * HIDDEN + n0;

#if HAS_TCGEN05
    extern __shared__ char smem[];
    const uint32_t sb = smem_u32(smem);

    if (wid == 0) TC_ALLOC(sb + SMEM_TMEM, 256);
    if (tid == 0)
        for (int s = 0; s < NSTG; s++) MBAR_INIT(sb + SMEM_CONS + 8 * s, 1);
    __syncthreads();
    uint32_t tmem;
    asm volatile("ld.shared.b32 %0, [%1];" : "=r"(tmem) : "r"(sb + SMEM_TMEM));
    if (wid == 0) TC_RELINQ();

    // A tasks (8): m = t>>3 (0..255), kb = t&7 (padded hbuf -> safe rows)
    uint32_t hoff[8], a_sw[8];
#pragma unroll
    for (int i = 0; i < 8; i++) {
        int t = tid + i * 256, m = t >> 3, kb = t & 7;
        hoff[i] = (uint32_t)(off + m0 + m) * (INTER / 2) + kb * 4;
        a_sw[i] = swz128((uint32_t)(m * 128 + kb * 16));
    }
    // W tasks (4): n = t&127, kb = t>>7 (0..7)
    const float* w2t[4]; uint32_t w_sw[4];
#pragma unroll
    for (int i = 0; i < 4; i++) {
        int t = tid + i * 256, n = t & 127, kb = t >> 7;
        w2t[i] = w2b + (size_t)(kb * 8) * HIDDEN + n;
        w_sw[i] = swz128((uint32_t)(n * 128 + kb * 16));
    }

    uint32_t apf[32], wpf[16];
    auto prefetch = [&](int c) {
#pragma unroll
        for (int i = 0; i < 8; i++) {
            uint4 v = *(const uint4*)(d_hbuf + hoff[i] + (size_t)c * 32);
            apf[4*i] = v.x; apf[4*i+1] = v.y; apf[4*i+2] = v.z; apf[4*i+3] = v.w;
        }
        const int k0 = c * BK_TC;
#pragma unroll
        for (int i = 0; i < 4; i++) {
            const float* p = w2t[i] + (size_t)k0 * HIDDEN;
            float t2[8];
#pragma unroll
            for (int j = 0; j < 8; j++) t2[j] = p[(size_t)j * HIDDEN];
#pragma unroll
            for (int j = 0; j < 4; j++) wpf[4*i+j] = packh2(t2[2*j], t2[2*j+1]);
        }
    };

    prefetch(0);
    const int NC = INTER / BK_TC;   // 88
    for (int c = 0; c < NC; c++) {
        const int s = c & 1;
        if (c >= NSTG) MBAR_WAIT(sb + SMEM_CONS + 8 * s, ((c >> 1) - 1) & 1);

        const uint32_t stg = sb + SMEM_DATA + s * G2_STAGE;
#pragma unroll
        for (int i = 0; i < 8; i++)
            STS128(stg + a_sw[i], apf[4*i], apf[4*i+1], apf[4*i+2], apf[4*i+3]);
#pragma unroll
        for (int i = 0; i < 4; i++)
            STS128(stg + A_TILE_B + w_sw[i], wpf[4*i], wpf[4*i+1], wpf[4*i+2], wpf[4*i+3]);
        __syncthreads();

        if (tid == 0) {
            FENCE_ASYNC();
            uint64_t bd = make_desc(stg + A_TILE_B);
#pragma unroll
            for (int mt = 0; mt < 2; mt++) {
                uint64_t ad = make_desc(stg + mt * (128 * 128));
#pragma unroll
                for (int ks = 0; ks < 4; ks++)
                    mma_f16_ss(tmem + mt * 128, ad + ks * 2, bd + ks * 2, IDESC_G2,
                               (c > 0 || ks > 0) ? 1u : 0u);
            }
            TC_COMMIT(sb + SMEM_CONS + 8 * s);
        }
        if (c + 1 < NC) prefetch(c + 1);
    }

    MBAR_WAIT(sb + SMEM_CONS + 8 * ((NC - 1) & 1), ((NC - 1) >> 1) & 1);
    TC_FENCE_AFTER();
    {
        const int mt = wid >> 2;
        const int mr = (wid & 3) * 32 + lid;
        const int r  = m0 + mt * 128 + mr;
        const bool ok = r < cnt;
        const int   tok = ok ? d_tok[off + r] : 0;
        const float wt  = ok ? d_wgt[off + r] : 0.f;
        float* orow = out + (size_t)tok * HIDDEN + n0;
        const uint32_t tb = tmem + mt * 128;
#pragma unroll
        for (int cc = 0; cc < 4; cc++) {
            const int cb = cc * 32;
            uint32_t yr[32];
            LDTM_X32(yr, tb + cb);
            TC_WAIT_LD();
            if (ok) {
#pragma unroll
                for (int j = 0; j < 32; j++)
                    atomicAdd(&orow[cb + j], wt * __uint_as_float(yr[j]));
            }
        }
    }
    __syncthreads();
    if (wid == 0) TC_DEALLOC(tmem, 256);

#else
    // ======= fallback: single-buffered mma.sync, 2 m-tiles sequential =======
    extern __shared__ uint32_t smw[];
    uint32_t* As = smw;
    uint32_t* Ws = As + 128 * FSTR;
    const int g = lid >> 2, tg = lid & 3;
    const int rg = (wid >> 2) * 64, cg = (wid & 3) * 32;

    for (int mt = 0; mt < 2; mt++) {
        const int mb = m0 + mt * 128;
        if (mb >= cnt) break;
        float acc[4][4][4];
#pragma unroll
        for (int mi = 0; mi < 4; mi++)
#pragma unroll
            for (int ni = 0; ni < 4; ni++)
#pragma unroll
                for (int r = 0; r < 4; r++) acc[mi][ni][r] = 0.f;

        for (int c = 0; c < INTER / BK_TC; c++) {
            const int k0 = c * BK_TC;
#pragma unroll
            for (int i = 0; i < 2; i++) {
                int t = tid + i * 256, m = t >> 3, kb = t & 7;
                uint4 v = *(const uint4*)(d_hbuf + (size_t)(off + mb + m) * (INTER/2)
                                          + k0/2 + kb * 4);
                uint32_t* p = &As[m * FSTR + kb * 4];
                p[0] = v.x; p[1] = v.y; p[2] = v.z; p[3] = v.w;
            }
#pragma unroll
            for (int i = 0; i < 4; i++) {
                int t = tid + i * 256, n = t & 127, kp = t >> 7;
                const float* p = w2b + (size_t)(k0 + kp * 8) * HIDDEN + n;
#pragma unroll
                for (int j = 0; j < 4; j++)
                    Ws[n * FSTR + kp * 4 + j] = packh2(p[(2*j)*HIDDEN], p[(2*j+1)*HIDDEN]);
            }
            __syncthreads();
#pragma unroll
            for (int kk = 0; kk < 4; kk++) {
                const int ko = kk * 8;
                uint32_t a[4][4];
#pragma unroll
                for (int mi = 0; mi < 4; mi++) {
                    int rb = rg + mi * 16;
                    a[mi][0] = As[(rb + g)     * FSTR + ko + tg];
                    a[mi][1] = As[(rb + g + 8) * FSTR + ko + tg];
                    a[mi][2] = As[(rb + g)     * FSTR + ko + tg + 4];
                    a[mi][3] = As[(rb + g + 8) * FSTR + ko + tg + 4];
                }
#pragma unroll
                for (int ni = 0; ni < 4; ni++) {
                    int cb = cg + ni * 8;
                    uint32_t b0 = Ws[(cb + g) * FSTR + ko + tg];
                    uint32_t b1 = Ws[(cb + g) * FSTR + ko + tg + 4];
#pragma unroll
                    for (int mi = 0; mi < 4; mi++)
                        mma16816(acc[mi][ni], a[mi], b0, b1);
                }
            }
            __syncthreads();
        }
#pragma unroll
        for (int mi = 0; mi < 4; mi++)
#pragma unroll
            for (int ni = 0; ni < 4; ni++) {
                int r0 = mb + rg + mi * 16 + g;
                int r1 = r0 + 8;
                int col = n0 + cg + ni * 8 + tg * 2;
                if (r0 < cnt) {
                    int tk = d_tok[off + r0]; float wt = d_wgt[off + r0];
                    atomicAdd(&out[(size_t)tk * HIDDEN + col],     wt * acc[mi][ni][0]);
                    atomicAdd(&out[(size_t)tk * HIDDEN + col + 1], wt * acc[mi][ni][1]);
                }
                if (r1 < cnt) {
                    int tk = d_tok[off + r1]; float wt = d_wgt[off + r1];
                    atomicAdd(&out[(size_t)tk * HIDDEN + col],     wt * acc[mi][ni][2]);
                    atomicAdd(&out[(size_t)tk * HIDDEN + col + 1], wt * acc[mi][ni][3]);
                }
            }
        __syncthreads();
    }
#endif
}

// ---------------------------------------------------------------------------
// launch — inputs: x, expert_weights, w1, w2, w3, expert_indices
// ---------------------------------------------------------------------------
extern "C" void kernel_launch(void* const* d_in, const int* in_sizes, int n_in,
                              void* d_out, int out_size) {
    const float* x  = (const float*)d_in[0];
    const float* ew = (const float*)d_in[1];
    const float* w1 = (const float*)d_in[2];
    const float* w2 = (const float*)d_in[3];
    const float* w3 = (const float*)d_in[4];
    const int*   ei = (const int*)d_in[5];
    float* out = (float*)d_out;

    static int attr_done = 0;
    if (!attr_done) {
        cudaFuncSetAttribute(gemm1_kernel, cudaFuncAttributeMaxDynamicSharedMemorySize, G1_SMEM);
        cudaFuncSetAttribute(gemm2_kernel, cudaFuncAttributeMaxDynamicSharedMemorySize, G2_SMEM);
        attr_done = 1;
    }

    cudaMemsetAsync(out, 0, sizeof(float) * (size_t)TOKENS * HIDDEN, 0);
    route_kernel<<<1, 256>>>(ei, ew);
    xgather_kernel<<<NPAIR + 256, 256>>>(x);

    dim3 g1(NEXP * MPAIR, INTER / BN1);   // 128 x 88
    gemm1_kernel<<<g1, 256, G1_SMEM>>>(w1, w3);

    dim3 g2(NEXP * MPAIR, HIDDEN / BN2);  // 128 x 16
    gemm2_kernel<<<g2, 256, G2_SMEM>>>(w2, out);
}

// round 16
// speedup vs baseline: 1.4201x; 1.0593x over previous
#include <cuda_runtime.h>
#include <cuda_fp16.h>
#include <cstdint>

// Problem constants
#define TOKENS 2048
#define HIDDEN 2048
#define INTER  5632
#define NEXP   8
#define TOPK   2
#define NPAIR  4096

#define MPAIR  16          // m-pair slots per expert (2x128 rows each)
#define BN1    64          // gemm1 n-tile
#define BN2    128         // gemm2 n-tile

// ---- tcgen05 config: fp16 K-major SW128, BK=64, NSTG=2, 2 CTAs/SM ----
#define BK_TC 64
#define NSTG  2
#define A_TILE_B  (256 * 128)            // 256 rows x 64k fp16 = 32 KB
#define W1_TILE_B (64 * 128)             // 8 KB
#define W2_TILE_B (128 * 128)            // 16 KB
#define G1_STAGE  (A_TILE_B + 2 * W1_TILE_B)   // 48 KB
#define G2_STAGE  (A_TILE_B + W2_TILE_B)       // 48 KB
#define SMEM_TMEM 0
#define SMEM_CONS 16
#define SMEM_DATA 1024
#define G1_SMEM (SMEM_DATA + NSTG * G1_STAGE)  // 99,328 -> 2 CTAs/SM
#define G2_SMEM (SMEM_DATA + NSTG * G2_STAGE)  // 99,328 -> 2 CTAs/SM

#define IDESC_G1 ((1u << 4) | ((BN1 / 8) << 17) | (8u << 24))   // M=128,N=64
#define IDESC_G2 ((1u << 4) | ((BN2 / 8) << 17) | (8u << 24))   // M=128,N=128

#define FSTR 36   // fallback smem stride

#if defined(__CUDA_ARCH__) && defined(__CUDA_ARCH_FEAT_SM103_ALL)
#define HAS_TCGEN05 1
#else
#define HAS_TCGEN05 0
#endif

// -------- persistent device scratch --------
__device__ int      d_cnt[NEXP];
__device__ int      d_off[NEXP];
__device__ int      d_tok[NPAIR];
__device__ int      d_pos[NPAIR];
__device__ float    d_wgt[NPAIR];
__device__ uint32_t d_xg[(size_t)(NPAIR + 256) * (HIDDEN / 2)];   // sorted x fp16 + pad
__device__ uint32_t d_hbuf[(size_t)(NPAIR + 256) * (INTER / 2)];  // h fp16, padded
__device__ float    d_ybuf[(size_t)NPAIR * HIDDEN];               // weighted y (sorted)

// ---------------------------------------------------------------------------
// helpers
// ---------------------------------------------------------------------------
__device__ __forceinline__ uint32_t packh2(float lo, float hi) {
    __half2 h = __floats2half2_rn(lo, hi);
    return *reinterpret_cast<uint32_t*>(&h);
}
__device__ __forceinline__ void mma16816(float c[4], const uint32_t a[4],
                                         uint32_t b0, uint32_t b1) {
    asm volatile(
        "mma.sync.aligned.m16n8k16.row.col.f32.f16.f16.f32 "
        "{%0,%1,%2,%3}, {%4,%5,%6,%7}, {%8,%9}, {%0,%1,%2,%3};\n"
        : "+f"(c[0]), "+f"(c[1]), "+f"(c[2]), "+f"(c[3])
        : "r"(a[0]), "r"(a[1]), "r"(a[2]), "r"(a[3]), "r"(b0), "r"(b1));
}
#define STS128(a, q0, q1, q2, q3)                                                 \
    asm volatile("st.shared.v4.b32 [%0], {%1,%2,%3,%4};"                          \
        :: "r"(a), "r"(q0), "r"(q1), "r"(q2), "r"(q3) : "memory")

#if HAS_TCGEN05
__device__ __forceinline__ uint32_t smem_u32(const void* p) {
    uint32_t a;
    asm("{ .reg .u64 t; cvta.to.shared.u64 t, %1; cvt.u32.u64 %0, t; }" : "=r"(a) : "l"(p));
    return a;
}
__device__ __forceinline__ uint32_t swz128(uint32_t b) { return b ^ ((b >> 3) & 0x70); }
static __device__ __forceinline__ uint64_t make_desc(uint32_t addr) {
    // K-major SW128: layout=2, version=1, SBO=64, LBO=1
    return ((uint64_t)2 << 61) | ((uint64_t)1 << 46) | ((uint64_t)64 << 32) |
           ((uint64_t)1 << 16) | ((uint64_t)(addr >> 4) & 0x3FFF);
}

#define MBAR_INIT(a, c) \
    asm volatile("mbarrier.init.shared.b64 [%0], %1;" :: "r"(a), "r"(c) : "memory")
#define MBAR_WAIT(a, ph) do {                                                     \
    uint32_t _m = (a), _p = (ph), _d;                                             \
    asm volatile("{\n\t.reg .pred p;\n\t"                                         \
        "mbarrier.try_wait.parity.acquire.cta.shared::cta.b64 p, [%1], %2;\n\t"   \
        "selp.b32 %0, 1, 0, p;\n\t}" : "=r"(_d) : "r"(_m), "r"(_p) : "memory");   \
    if (!_d) {                                                                     \
        asm volatile("{\n\t.reg .pred P1;\n\t"                                    \
        "W%=:\n\t"                                                                \
        "mbarrier.try_wait.parity.acquire.cta.shared::cta.b64 P1, [%0], %1, 0x989680;\n\t" \
        "@P1 bra.uni D%=;\n\t bra.uni W%=;\n\t D%=:\n\t}"                        \
        :: "r"(_m), "r"(_p) : "memory");                                          \
    } } while (0)

#define TC_ALLOC(sa, n)  asm volatile("tcgen05.alloc.cta_group::1.sync.aligned.shared::cta.b32 [%0], %1;" :: "r"(sa), "r"(n) : "memory")
#define TC_DEALLOC(t, n) asm volatile("tcgen05.dealloc.cta_group::1.sync.aligned.b32 %0, %1;" :: "r"(t), "r"(n))
#define TC_RELINQ()      asm volatile("tcgen05.relinquish_alloc_permit.cta_group::1.sync.aligned;")
#define TC_COMMIT(a)     asm volatile("tcgen05.commit.cta_group::1.mbarrier::arrive::one.shared::cluster.b64 [%0];" :: "r"(a) : "memory")
#define TC_FENCE_AFTER() asm volatile("tcgen05.fence::after_thread_sync;" ::: "memory")
#define TC_WAIT_LD()     asm volatile("tcgen05.wait::ld.sync.aligned;" ::: "memory")
#define FENCE_ASYNC()    asm volatile("fence.proxy.async.shared::cta;" ::: "memory")

__device__ __forceinline__ void mma_f16_ss(uint32_t d, uint64_t ad, uint64_t bd,
                                           uint32_t idesc, uint32_t en) {
    asm volatile(
        "{\n\t.reg .pred p;\n\t"
        "setp.ne.u32 p, %4, 0;\n\t"
        "tcgen05.mma.cta_group::1.kind::f16 [%0], %1, %2, %3, {%5, %5, %5, %5}, p;\n\t"
        "}" :: "r"(d), "l"(ad), "l"(bd), "r"(idesc), "r"(en), "r"(0u) : "memory");
}

#define LDTM_X32(r, a)                                                            \
    asm volatile("tcgen05.ld.sync.aligned.32x32b.x32.b32 "                        \
        "{%0,%1,%2,%3,%4,%5,%6,%7,%8,%9,%10,%11,%12,%13,%14,%15,"                 \
        "%16,%17,%18,%19,%20,%21,%22,%23,%24,%25,%26,%27,%28,%29,%30,%31}, [%32];"\
        : "=r"((r)[0]),"=r"((r)[1]),"=r"((r)[2]),"=r"((r)[3]),                    \
          "=r"((r)[4]),"=r"((r)[5]),"=r"((r)[6]),"=r"((r)[7]),                    \
          "=r"((r)[8]),"=r"((r)[9]),"=r"((r)[10]),"=r"((r)[11]),                  \
          "=r"((r)[12]),"=r"((r)[13]),"=r"((r)[14]),"=r"((r)[15]),                \
          "=r"((r)[16]),"=r"((r)[17]),"=r"((r)[18]),"=r"((r)[19]),                \
          "=r"((r)[20]),"=r"((r)[21]),"=r"((r)[22]),"=r"((r)[23]),                \
          "=r"((r)[24]),"=r"((r)[25]),"=r"((r)[26]),"=r"((r)[27]),                \
          "=r"((r)[28]),"=r"((r)[29]),"=r"((r)[30]),"=r"((r)[31]) : "r"(a))
#endif  // HAS_TCGEN05

// ---------------------------------------------------------------------------
// Routing (+ inverse permutation + per-slot weight) and gather
// ---------------------------------------------------------------------------
__global__ void route_kernel(const int* __restrict__ eidx,
                             const float* __restrict__ ew) {
    __shared__ int s_cnt[NEXP], s_off[NEXP], s_cur[NEXP];
    int t = threadIdx.x;
    if (t < NEXP) s_cnt[t] = 0;
    __syncthreads();
    for (int p = t; p < NPAIR; p += blockDim.x) atomicAdd(&s_cnt[eidx[p]], 1);
    __syncthreads();
    if (t == 0) {
        int o = 0;
        for (int e = 0; e < NEXP; e++) { s_off[e] = o; s_cur[e] = o; o += s_cnt[e]; }
    }
    __syncthreads();
    for (int p = t; p < NPAIR; p += blockDim.x) {
        int pos = atomicAdd(&s_cur[eidx[p]], 1);
        d_tok[pos] = p >> 1;
        d_pos[p]   = pos;
        d_wgt[pos] = ew[p];
    }
    if (t < NEXP) { d_cnt[t] = s_cnt[t]; d_off[t] = s_off[t]; }
}

__global__ __launch_bounds__(256)
void xgather_kernel(const float* __restrict__ x) {
    const int slot = blockIdx.x;
    uint32_t* dst = d_xg + (size_t)slot * (HIDDEN / 2);
    if (slot < NPAIR) {
        const float* src = x + (size_t)d_tok[slot] * HIDDEN;
        for (int i = threadIdx.x; i < HIDDEN / 8; i += 256) {
            float4 v0 = *(const float4*)(src + i * 8);
            float4 v1 = *(const float4*)(src + i * 8 + 4);
            *(uint4*)(dst + i * 4) = make_uint4(packh2(v0.x, v0.y), packh2(v0.z, v0.w),
                                                packh2(v1.x, v1.y), packh2(v1.z, v1.w));
        }
    } else {
        for (int i = threadIdx.x; i < HIDDEN / 8; i += 256)
            *(uint4*)(dst + i * 4) = make_uint4(0, 0, 0, 0);
    }
}

// ---------------------------------------------------------------------------
// GEMM1: per CTA: 2 m-tiles (256 rows) x N=64; gate/up fused; h -> d_hbuf fp16
// TMEM: gate0@0, up0@64, gate1@128, up1@192.
// ---------------------------------------------------------------------------
__global__ __launch_bounds__(256, 2)
void gemm1_kernel(const float* __restrict__ w1g,
                  const float* __restrict__ w3g) {
    const int e    = blockIdx.x >> 4;
    const int cnt  = d_cnt[e];
    const int m0   = (blockIdx.x & 15) * 256;
    if (m0 >= cnt) return;
    const int n0   = blockIdx.y * BN1;
    const int off  = d_off[e];
    const int tid = threadIdx.x, wid = tid >> 5, lid = tid & 31;

    const float* w1b = w1g + (size_t)e * HIDDEN * INTER + n0;
    const float* w3b = w3g + (size_t)e * HIDDEN * INTER + n0;

#if HAS_TCGEN05
    extern __shared__ char smem[];
    const uint32_t sb = smem_u32(smem);

    if (wid == 0) TC_ALLOC(sb + SMEM_TMEM, 256);
    if (tid == 0)
        for (int s = 0; s < NSTG; s++) MBAR_INIT(sb + SMEM_CONS + 8 * s, 1);
    __syncthreads();
    uint32_t tmem;
    asm volatile("ld.shared.b32 %0, [%1];" : "=r"(tmem) : "r"(sb + SMEM_TMEM));
    if (wid == 0) TC_RELINQ();

    // A tasks (8): t = tid + i*256 -> m = t>>3 (0..255), kb = t&7 (16B block)
    uint32_t xoff[8], a_sw[8];
#pragma unroll
    for (int i = 0; i < 8; i++) {
        int t = tid + i * 256, m = t >> 3, kb = t & 7;
        xoff[i] = (uint32_t)(off + m0 + m) * (HIDDEN / 2) + kb * 4;
        a_sw[i] = swz128((uint32_t)(m * 128 + kb * 16));
    }
    // W tasks (2 per matrix): t -> n = t&63, kb = t>>6 (0..7)
    const float *w1t[2], *w3t[2]; uint32_t w_sw[2];
#pragma unroll
    for (int i = 0; i < 2; i++) {
        int t = tid + i * 256, n = t & 63, kb = t >> 6;
        w1t[i] = w1b + (size_t)(kb * 8) * INTER + n;
        w3t[i] = w3b + (size_t)(kb * 8) * INTER + n;
        w_sw[i] = swz128((uint32_t)(n * 128 + kb * 16));
    }

    uint32_t apf[32], w1pf[8], w3pf[8];
    auto prefetch = [&](int k0) {
        const int kw = k0 / 2;
#pragma unroll
        for (int i = 0; i < 8; i++) {
            uint4 v = *(const uint4*)(d_xg + xoff[i] + kw);
            apf[4*i] = v.x; apf[4*i+1] = v.y; apf[4*i+2] = v.z; apf[4*i+3] = v.w;
        }
#pragma unroll
        for (int i = 0; i < 2; i++) {
            const float* p1 = w1t[i] + (size_t)k0 * INTER;
            const float* p3 = w3t[i] + (size_t)k0 * INTER;
            float t1[8], t3[8];
#pragma unroll
            for (int j = 0; j < 8; j++) {
                t1[j] = p1[(size_t)j * INTER];
                t3[j] = p3[(size_t)j * INTER];
            }
#pragma unroll
            for (int j = 0; j < 4; j++) {
                w1pf[4*i+j] = packh2(t1[2*j], t1[2*j+1]);
                w3pf[4*i+j] = packh2(t3[2*j], t3[2*j+1]);
            }
        }
    };

    prefetch(0);
    const int NC = HIDDEN / BK_TC;   // 32
    for (int c = 0; c < NC; c++) {
        const int s = c & 1;
        if (c >= NSTG) MBAR_WAIT(sb + SMEM_CONS + 8 * s, ((c >> 1) - 1) & 1);

        const uint32_t stg = sb + SMEM_DATA + s * G1_STAGE;
#pragma unroll
        for (int i = 0; i < 8; i++)
            STS128(stg + a_sw[i], apf[4*i], apf[4*i+1], apf[4*i+2], apf[4*i+3]);
#pragma unroll
        for (int i = 0; i < 2; i++) {
            STS128(stg + A_TILE_B + w_sw[i], w1pf[4*i], w1pf[4*i+1], w1pf[4*i+2], w1pf[4*i+3]);
            STS128(stg + A_TILE_B + W1_TILE_B + w_sw[i], w3pf[4*i], w3pf[4*i+1], w3pf[4*i+2], w3pf[4*i+3]);
        }
        __syncthreads();

        if (tid == 0) {
            FENCE_ASYNC();
            uint64_t b1 = make_desc(stg + A_TILE_B);
            uint64_t b3 = make_desc(stg + A_TILE_B + W1_TILE_B);
#pragma unroll
            for (int mt = 0; mt < 2; mt++) {
                uint64_t ad = make_desc(stg + mt * (128 * 128));
#pragma unroll
                for (int ks = 0; ks < 4; ks++) {
                    uint32_t en = (c > 0 || ks > 0) ? 1u : 0u;
                    mma_f16_ss(tmem + mt * 128,      ad + ks * 2, b1 + ks * 2, IDESC_G1, en);
                    mma_f16_ss(tmem + mt * 128 + 64, ad + ks * 2, b3 + ks * 2, IDESC_G1, en);
                }
            }
            TC_COMMIT(sb + SMEM_CONS + 8 * s);
        }
        if (c + 1 < NC) prefetch((c + 1) * BK_TC);
    }

    MBAR_WAIT(sb + SMEM_CONS + 8 * ((NC - 1) & 1), ((NC - 1) >> 1) & 1);
    TC_FENCE_AFTER();
    {
        // warps 0-3: m-tile 0, warps 4-7: m-tile 1; subpartition = wid&3
        const int mt = wid >> 2;
        const int mr = (wid & 3) * 32 + lid;
        const int r  = m0 + mt * 128 + mr;
        const bool ok = r < cnt;
        uint32_t* hrow = d_hbuf + (size_t)(off + r) * (INTER / 2) + n0 / 2;
        const uint32_t tb = tmem + mt * 128;
#pragma unroll
        for (int cc = 0; cc < 2; cc++) {
            const int cb = cc * 32;
            uint32_t gr[32], ur[32];
            LDTM_X32(gr, tb + cb);
            LDTM_X32(ur, tb + 64 + cb);
            TC_WAIT_LD();
            if (ok) {
                uint32_t hw[16];
#pragma unroll
                for (int j = 0; j < 16; j++) {
                    float g0 = __uint_as_float(gr[2*j]);
                    float g1 = __uint_as_float(gr[2*j+1]);
                    float h0 = g0 / (1.f + __expf(-g0)) * __uint_as_float(ur[2*j]);
                    float h1 = g1 / (1.f + __expf(-g1)) * __uint_as_float(ur[2*j+1]);
                    hw[j] = packh2(h0, h1);
                }
#pragma unroll
                for (int j = 0; j < 16; j += 4)
                    *(uint4*)(hrow + cb/2 + j) = make_uint4(hw[j], hw[j+1], hw[j+2], hw[j+3]);
            }
        }
    }
    __syncthreads();
    if (wid == 0) TC_DEALLOC(tmem, 256);

#else
    // ======= fallback: single-buffered mma.sync, 2 m-tiles sequential =======
    extern __shared__ uint32_t smw[];
    uint32_t* As  = smw;
    uint32_t* W1s = As + 128 * FSTR;
    uint32_t* W3s = W1s + 64 * FSTR;
    const int g = lid >> 2, tg = lid & 3;
    const int rg = (wid >> 1) * 32, cg = (wid & 1) * 32;

    for (int mt = 0; mt < 2; mt++) {
        const int mb = m0 + mt * 128;
        if (mb >= cnt) break;
        float gacc[2][4][4], uacc[2][4][4];
#pragma unroll
        for (int mi = 0; mi < 2; mi++)
#pragma unroll
            for (int ni = 0; ni < 4; ni++)
#pragma unroll
                for (int r = 0; r < 4; r++) { gacc[mi][ni][r] = 0.f; uacc[mi][ni][r] = 0.f; }

        for (int c = 0; c < HIDDEN / BK_TC; c++) {
            const int k0 = c * BK_TC;
#pragma unroll
            for (int i = 0; i < 2; i++) {
                int t = tid + i * 256, m = t >> 3, kb = t & 7;
                uint4 v = *(const uint4*)(d_xg + (size_t)(off + mb + m) * (HIDDEN/2) + k0/2 + kb * 4);
                uint32_t* p = &As[m * FSTR + kb * 4];
                p[0] = v.x; p[1] = v.y; p[2] = v.z; p[3] = v.w;
            }
#pragma unroll
            for (int i = 0; i < 2; i++) {
                int t = tid + i * 256, n = t & 63, kp = t >> 6;
                const float* p1 = w1b + (size_t)(k0 + kp * 8) * INTER + n;
                const float* p3 = w3b + (size_t)(k0 + kp * 8) * INTER + n;
#pragma unroll
                for (int j = 0; j < 4; j++) {
                    W1s[n * FSTR + kp * 4 + j] = packh2(p1[(2*j)*INTER], p1[(2*j+1)*INTER]);
                    W3s[n * FSTR + kp * 4 + j] = packh2(p3[(2*j)*INTER], p3[(2*j+1)*INTER]);
                }
            }
            __syncthreads();
#pragma unroll
            for (int kk = 0; kk < 4; kk++) {
                const int ko = kk * 8;
                uint32_t a[2][4];
#pragma unroll
                for (int mi = 0; mi < 2; mi++) {
                    int rb = rg + mi * 16;
                    a[mi][0] = As[(rb + g)     * FSTR + ko + tg];
                    a[mi][1] = As[(rb + g + 8) * FSTR + ko + tg];
                    a[mi][2] = As[(rb + g)     * FSTR + ko + tg + 4];
                    a[mi][3] = As[(rb + g + 8) * FSTR + ko + tg + 4];
                }
#pragma unroll
                for (int ni = 0; ni < 4; ni++) {
                    int cb = cg + ni * 8;
                    uint32_t b0 = W1s[(cb + g) * FSTR + ko + tg];
                    uint32_t b1 = W1s[(cb + g) * FSTR + ko + tg + 4];
                    uint32_t c0 = W3s[(cb + g) * FSTR + ko + tg];
                    uint32_t c1 = W3s[(cb + g) * FSTR + ko + tg + 4];
                    mma16816(gacc[0][ni], a[0], b0, b1);
                    mma16816(gacc[1][ni], a[1], b0, b1);
                    mma16816(uacc[0][ni], a[0], c0, c1);
                    mma16816(uacc[1][ni], a[1], c0, c1);
                }
            }
            __syncthreads();
        }
#pragma unroll
        for (int mi = 0; mi < 2; mi++)
#pragma unroll
            for (int ni = 0; ni < 4; ni++) {
                int r0 = mb + rg + mi * 16 + g;
                int r1 = r0 + 8;
                int col = n0 + cg + ni * 8 + tg * 2;
                if (r0 < cnt) {
                    float g0 = gacc[mi][ni][0], g1 = gacc[mi][ni][1];
                    float h0 = g0 / (1.f + __expf(-g0)) * uacc[mi][ni][0];
                    float h1 = g1 / (1.f + __expf(-g1)) * uacc[mi][ni][1];
                    d_hbuf[((size_t)(off + r0) * INTER + col) >> 1] = packh2(h0, h1);
                }
                if (r1 < cnt) {
                    float g2 = gacc[mi][ni][2], g3 = gacc[mi][ni][3];
                    float h2 = g2 / (1.f + __expf(-g2)) * uacc[mi][ni][2];
                    float h3 = g3 / (1.f + __expf(-g3)) * uacc[mi][ni][3];
                    d_hbuf[((size_t)(off + r1) * INTER + col) >> 1] = packh2(h2, h3);
                }
            }
        __syncthreads();
    }
#endif
}

// ---------------------------------------------------------------------------
// GEMM2: per CTA: 2 m-tiles (256 rows) x N=128; writes wt*y -> d_ybuf (sorted,
// coalesced). TMEM: y0@0, y1@128.
// ---------------------------------------------------------------------------
__global__ __launch_bounds__(256, 2)
void gemm2_kernel(const float* __restrict__ w2g) {
    const int e    = blockIdx.x >> 4;
    const int cnt  = d_cnt[e];
    const int m0   = (blockIdx.x & 15) * 256;
    if (m0 >= cnt) return;
    const int n0   = blockIdx.y * BN2;
    const int off  = d_off[e];
    const int tid = threadIdx.x, wid = tid >> 5, lid = tid & 31;

    const float* w2b = w2g + (size_t)e * INTER * HIDDEN + n0;

#if HAS_TCGEN05
    extern __shared__ char smem[];
    const uint32_t sb = smem_u32(smem);

    if (wid == 0) TC_ALLOC(sb + SMEM_TMEM, 256);
    if (tid == 0)
        for (int s = 0; s < NSTG; s++) MBAR_INIT(sb + SMEM_CONS + 8 * s, 1);
    __syncthreads();
    uint32_t tmem;
    asm volatile("ld.shared.b32 %0, [%1];" : "=r"(tmem) : "r"(sb + SMEM_TMEM));
    if (wid == 0) TC_RELINQ();

    // A tasks (8): m = t>>3 (0..255), kb = t&7 (padded hbuf -> safe rows)
    uint32_t hoff[8], a_sw[8];
#pragma unroll
    for (int i = 0; i < 8; i++) {
        int t = tid + i * 256, m = t >> 3, kb = t & 7;
        hoff[i] = (uint32_t)(off + m0 + m) * (INTER / 2) + kb * 4;
        a_sw[i] = swz128((uint32_t)(m * 128 + kb * 16));
    }
    // W tasks (4): n = t&127, kb = t>>7 (0..7)
    const float* w2t[4]; uint32_t w_sw[4];
#pragma unroll
    for (int i = 0; i < 4; i++) {
        int t = tid + i * 256, n = t & 127, kb = t >> 7;
        w2t[i] = w2b + (size_t)(kb * 8) * HIDDEN + n;
        w_sw[i] = swz128((uint32_t)(n * 128 + kb * 16));
    }

    uint32_t apf[32], wpf[16];
    auto prefetch = [&](int c) {
#pragma unroll
        for (int i = 0; i < 8; i++) {
            uint4 v = *(const uint4*)(d_hbuf + hoff[i] + (size_t)c * 32);
            apf[4*i] = v.x; apf[4*i+1] = v.y; apf[4*i+2] = v.z; apf[4*i+3] = v.w;
        }
        const int k0 = c * BK_TC;
#pragma unroll
        for (int i = 0; i < 4; i++) {
            const float* p = w2t[i] + (size_t)k0 * HIDDEN;
            float t2[8];
#pragma unroll
            for (int j = 0; j < 8; j++) t2[j] = p[(size_t)j * HIDDEN];
#pragma unroll
            for (int j = 0; j < 4; j++) wpf[4*i+j] = packh2(t2[2*j], t2[2*j+1]);
        }
    };

    prefetch(0);
    const int NC = INTER / BK_TC;   // 88
    for (int c = 0; c < NC; c++) {
        const int s = c & 1;
        if (c >= NSTG) MBAR_WAIT(sb + SMEM_CONS + 8 * s, ((c >> 1) - 1) & 1);

        const uint32_t stg = sb + SMEM_DATA + s * G2_STAGE;
#pragma unroll
        for (int i = 0; i < 8; i++)
            STS128(stg + a_sw[i], apf[4*i], apf[4*i+1], apf[4*i+2], apf[4*i+3]);
#pragma unroll
        for (int i = 0; i < 4; i++)
            STS128(stg + A_TILE_B + w_sw[i], wpf[4*i], wpf[4*i+1], wpf[4*i+2], wpf[4*i+3]);
        __syncthreads();

        if (tid == 0) {
            FENCE_ASYNC();
            uint64_t bd = make_desc(stg + A_TILE_B);
#pragma unroll
            for (int mt = 0; mt < 2; mt++) {
                uint64_t ad = make_desc(stg + mt * (128 * 128));
#pragma unroll
                for (int ks = 0; ks < 4; ks++)
                    mma_f16_ss(tmem + mt * 128, ad + ks * 2, bd + ks * 2, IDESC_G2,
                               (c > 0 || ks > 0) ? 1u : 0u);
            }
            TC_COMMIT(sb + SMEM_CONS + 8 * s);
        }
        if (c + 1 < NC) prefetch(c + 1);
    }

    MBAR_WAIT(sb + SMEM_CONS + 8 * ((NC - 1) & 1), ((NC - 1) >> 1) & 1);
    TC_FENCE_AFTER();
    {
        const int mt = wid >> 2;
        const int mr = (wid & 3) * 32 + lid;
        const int r  = m0 + mt * 128 + mr;
        const bool ok = r < cnt;
        const float wt = ok ? d_wgt[off + r] : 0.f;
        float* yrow = d_ybuf + (size_t)(off + r) * HIDDEN + n0;
        const uint32_t tb = tmem + mt * 128;
#pragma unroll
        for (int cc = 0; cc < 4; cc++) {
            const int cb = cc * 32;
            uint32_t yr[32];
            LDTM_X32(yr, tb + cb);
            TC_WAIT_LD();
            if (ok) {
#pragma unroll
                for (int j = 0; j < 32; j += 4) {
                    float4 v;
                    v.x = wt * __uint_as_float(yr[j]);
                    v.y = wt * __uint_as_float(yr[j+1]);
                    v.z = wt * __uint_as_float(yr[j+2]);
                    v.w = wt * __uint_as_float(yr[j+3]);
                    *(float4*)(yrow + cb + j) = v;
                }
            }
        }
    }
    __syncthreads();
    if (wid == 0) TC_DEALLOC(tmem, 256);

#else
    // ======= fallback: single-buffered mma.sync, 2 m-tiles sequential =======
    extern __shared__ uint32_t smw[];
    uint32_t* As = smw;
    uint32_t* Ws = As + 128 * FSTR;
    const int g = lid >> 2, tg = lid & 3;
    const int rg = (wid >> 2) * 64, cg = (wid & 3) * 32;

    for (int mt = 0; mt < 2; mt++) {
        const int mb = m0 + mt * 128;
        if (mb >= cnt) break;
        float acc[4][4][4];
#pragma unroll
        for (int mi = 0; mi < 4; mi++)
#pragma unroll
            for (int ni = 0; ni < 4; ni++)
#pragma unroll
                for (int r = 0; r < 4; r++) acc[mi][ni][r] = 0.f;

        for (int c = 0; c < INTER / BK_TC; c++) {
            const int k0 = c * BK_TC;
#pragma unroll
            for (int i = 0; i < 2; i++) {
                int t = tid + i * 256, m = t >> 3, kb = t & 7;
                uint4 v = *(const uint4*)(d_hbuf + (size_t)(off + mb + m) * (INTER/2)
                                          + k0/2 + kb * 4);
                uint32_t* p = &As[m * FSTR + kb * 4];
                p[0] = v.x; p[1] = v.y; p[2] = v.z; p[3] = v.w;
            }
#pragma unroll
            for (int i = 0; i < 4; i++) {
                int t = tid + i * 256, n = t & 127, kp = t >> 7;
                const float* p = w2b + (size_t)(k0 + kp * 8) * HIDDEN + n;
#pragma unroll
                for (int j = 0; j < 4; j++)
                    Ws[n * FSTR + kp * 4 + j] = packh2(p[(2*j)*HIDDEN], p[(2*j+1)*HIDDEN]);
            }
            __syncthreads();
#pragma unroll
            for (int kk = 0; kk < 4; kk++) {
                const int ko = kk * 8;
                uint32_t a[4][4];
#pragma unroll
                for (int mi = 0; mi < 4; mi++) {
                    int rb = rg + mi * 16;
                    a[mi][0] = As[(rb + g)     * FSTR + ko + tg];
                    a[mi][1] = As[(rb + g + 8) * FSTR + ko + tg];
                    a[mi][2] = As[(rb + g)     * FSTR + ko + tg + 4];
                    a[mi][3] = As[(rb + g + 8) * FSTR + ko + tg + 4];
                }
#pragma unroll
                for (int ni = 0; ni < 4; ni++) {
                    int cb = cg + ni * 8;
                    uint32_t b0 = Ws[(cb + g) * FSTR + ko + tg];
                    uint32_t b1 = Ws[(cb + g) * FSTR + ko + tg + 4];
#pragma unroll
                    for (int mi = 0; mi < 4; mi++)
                        mma16816(acc[mi][ni], a[mi], b0, b1);
                }
            }
            __syncthreads();
        }
#pragma unroll
        for (int mi = 0; mi < 4; mi++)
#pragma unroll
            for (int ni = 0; ni < 4; ni++) {
                int r0 = mb + rg + mi * 16 + g;
                int r1 = r0 + 8;
                int col = n0 + cg + ni * 8 + tg * 2;
                if (r0 < cnt) {
                    float wt = d_wgt[off + r0];
                    *(float2*)(d_ybuf + (size_t)(off + r0) * HIDDEN + col) =
                        make_float2(wt * acc[mi][ni][0], wt * acc[mi][ni][1]);
                }
                if (r1 < cnt) {
                    float wt = d_wgt[off + r1];
                    *(float2*)(d_ybuf + (size_t)(off + r1) * HIDDEN + col) =
                        make_float2(wt * acc[mi][ni][2], wt * acc[mi][ni][3]);
                }
            }
        __syncthreads();
    }
#endif
}

// ---------------------------------------------------------------------------
// Combine: out[t] = ybuf[pos[2t]] + ybuf[pos[2t+1]]  (y already weighted)
// ---------------------------------------------------------------------------
__global__ __launch_bounds__(256)
void combine_kernel(float* __restrict__ out) {
    const int t = blockIdx.x;
    const int p0 = d_pos[2 * t], p1 = d_pos[2 * t + 1];
    const float4* y0 = (const float4*)(d_ybuf + (size_t)p0 * HIDDEN);
    const float4* y1 = (const float4*)(d_ybuf + (size_t)p1 * HIDDEN);
    float4* o = (float4*)(out + (size_t)t * HIDDEN);
#pragma unroll
    for (int i = threadIdx.x; i < HIDDEN / 4; i += 256) {
        float4 a = y0[i], b = y1[i], r;
        r.x = a.x + b.x; r.y = a.y + b.y;
        r.z = a.z + b.z; r.w = a.w + b.w;
        o[i] = r;
    }
}

// ---------------------------------------------------------------------------
// launch — inputs: x, expert_weights, w1, w2, w3, expert_indices
// ---------------------------------------------------------------------------
extern "C" void kernel_launch(void* const* d_in, const int* in_sizes, int n_in,
                              void* d_out, int out_size) {
    const float* x  = (const float*)d_in[0];
    const float* ew = (const float*)d_in[1];
    const float* w1 = (const float*)d_in[2];
    const float* w2 = (const float*)d_in[3];
    const float* w3 = (const float*)d_in[4];
    const int*   ei = (const int*)d_in[5];
    float* out = (float*)d_out;

    static int attr_done = 0;
    if (!attr_done) {
        cudaFuncSetAttribute(gemm1_kernel, cudaFuncAttributeMaxDynamicSharedMemorySize, G1_SMEM);
        cudaFuncSetAttribute(gemm2_kernel, cudaFuncAttributeMaxDynamicSharedMemorySize, G2_SMEM);
        attr_done = 1;
    }

    route_kernel<<<1, 256>>>(ei, ew);
    xgather_kernel<<<NPAIR + 256, 256>>>(x);

    dim3 g1(NEXP * MPAIR, INTER / BN1);   // 128 x 88
    gemm1_kernel<<<g1, 256, G1_SMEM>>>(w1, w3);

    dim3 g2(NEXP * MPAIR, HIDDEN / BN2);  // 128 x 16
    gemm2_kernel<<<g2, 256, G2_SMEM>>>(w2);

    combine_kernel<<<TOKENS, 256>>>(out);
}